// round 1
// baseline (speedup 1.0000x reference)
#include <cuda_runtime.h>

// Causal attention, B=4, S=4096, D=64, fp32.
// Outputs (concatenated): attn_vec [B,S,D], attn_weights [B,S,S].

constexpr int Bb = 4;
constexpr int Ss = 4096;
constexpr int Dh = 64;
constexpr int BQ = 64;
constexpr int BK = 64;
constexpr int LD = 68;   // padded smem leading dim (keeps float4 alignment, spreads banks)

constexpr int SMEM_FLOATS = 4 * Dh * LD;            // Qs, Ks, Vs, Ps (all 64 x 68)
constexpr int SMEM_BYTES  = SMEM_FLOATS * 4;        // 69632 B

__device__ float g_inv[Bb * Ss];   // 1/rowsum per (b, q) row

__global__ __launch_bounds__(256)
void attn_fwd(const float* __restrict__ Q, const float* __restrict__ K,
              const float* __restrict__ V,
              float* __restrict__ out_vec, float* __restrict__ out_w)
{
    extern __shared__ float sm[];
    float* Qs = sm;                 // [Dh][LD]  Qs[d*LD + row]   (d-major)
    float* Ks = Qs + Dh * LD;       // [Dh][LD]  Ks[d*LD + col]   (d-major)
    float* Vs = Ks + Dh * LD;       // [BK][LD]  Vs[k*LD + d]     (natural)
    float* Ps = Vs + BK * LD;       // [BK][LD]  Ps[k*LD + row]   (k-major)

    const int b   = blockIdx.y;
    const int q0  = blockIdx.x * BQ;
    const int tid = threadIdx.x;
    const int tx  = tid & 15;
    const int ty  = tid >> 4;
    const int r0  = ty * 4;         // this thread's 4 query rows (tile-local)
    const int c0  = tx * 4;         // this thread's 4 key cols / out dims

    // ---- load Q tile, transposed to d-major ----
    const float* Qg = Q + ((size_t)(b * Ss + q0)) * Dh;
    #pragma unroll
    for (int idx = tid; idx < BQ * Dh / 4; idx += 256) {
        int row = idx >> 4;
        int d4  = (idx & 15) << 2;
        float4 v = *(const float4*)(Qg + row * Dh + d4);
        Qs[(d4 + 0) * LD + row] = v.x;
        Qs[(d4 + 1) * LD + row] = v.y;
        Qs[(d4 + 2) * LD + row] = v.z;
        Qs[(d4 + 3) * LD + row] = v.w;
    }

    float acc[4][4];
    #pragma unroll
    for (int i = 0; i < 4; i++)
        #pragma unroll
        for (int j = 0; j < 4; j++) acc[i][j] = 0.0f;
    float rsum[4] = {0.0f, 0.0f, 0.0f, 0.0f};

    const int ktiles = (q0 >> 6) + 1;   // only tiles intersecting the causal region

    for (int kt = 0; kt < ktiles; kt++) {
        const int k0 = kt * BK;
        __syncthreads();   // protect Ks/Vs/Ps from previous iteration's readers

        // ---- load K (transposed, d-major) and V (natural) tiles ----
        const float* Kg = K + ((size_t)(b * Ss + k0)) * Dh;
        const float* Vg = V + ((size_t)(b * Ss + k0)) * Dh;
        #pragma unroll
        for (int idx = tid; idx < BK * Dh / 4; idx += 256) {
            int row = idx >> 4;
            int d4  = (idx & 15) << 2;
            float4 kv = *(const float4*)(Kg + row * Dh + d4);
            Ks[(d4 + 0) * LD + row] = kv.x;
            Ks[(d4 + 1) * LD + row] = kv.y;
            Ks[(d4 + 2) * LD + row] = kv.z;
            Ks[(d4 + 3) * LD + row] = kv.w;
            *(float4*)(Vs + row * LD + d4) = *(const float4*)(Vg + row * Dh + d4);
        }
        __syncthreads();

        // ---- scores: 4x4 outer-product register blocking ----
        float s[4][4];
        #pragma unroll
        for (int i = 0; i < 4; i++)
            #pragma unroll
            for (int j = 0; j < 4; j++) s[i][j] = 0.0f;

        #pragma unroll 8
        for (int d = 0; d < Dh; d++) {
            float4 qv = *(const float4*)(Qs + d * LD + r0);
            float4 kv = *(const float4*)(Ks + d * LD + c0);
            float qa[4] = {qv.x, qv.y, qv.z, qv.w};
            float ka[4] = {kv.x, kv.y, kv.z, kv.w};
            #pragma unroll
            for (int i = 0; i < 4; i++)
                #pragma unroll
                for (int j = 0; j < 4; j++) s[i][j] += qa[i] * ka[j];
        }

        // ---- mask + exp (unnormalized softmax), stage to smem & gmem ----
        #pragma unroll
        for (int i = 0; i < 4; i++) {
            const int qr = q0 + r0 + i;
            #pragma unroll
            for (int j = 0; j < 4; j++) {
                const int kc = k0 + c0 + j;
                float p = (kc <= qr) ? __expf(s[i][j] * 0.125f) : 0.0f;
                s[i][j] = p;
                rsum[i] += p;
                Ps[(c0 + j) * LD + (r0 + i)] = p;
            }
        }
        float* Wg = out_w + ((size_t)(b * Ss + q0 + r0)) * Ss + (k0 + c0);
        #pragma unroll
        for (int i = 0; i < 4; i++)
            *(float4*)(Wg + (size_t)i * Ss) =
                make_float4(s[i][0], s[i][1], s[i][2], s[i][3]);

        __syncthreads();   // Ps fully written

        // ---- PV: acc[r][d] += P[r][k] * V[k][d] ----
        #pragma unroll 8
        for (int k = 0; k < BK; k++) {
            float4 pv = *(const float4*)(Ps + k * LD + r0);
            float4 vv = *(const float4*)(Vs + k * LD + c0);
            float pa[4] = {pv.x, pv.y, pv.z, pv.w};
            float va[4] = {vv.x, vv.y, vv.z, vv.w};
            #pragma unroll
            for (int i = 0; i < 4; i++)
                #pragma unroll
                for (int j = 0; j < 4; j++) acc[i][j] += pa[i] * va[j];
        }
    }

    // ---- reduce row sums across the 16 tx lanes (within-warp) ----
    #pragma unroll
    for (int m = 8; m >= 1; m >>= 1)
        #pragma unroll
        for (int i = 0; i < 4; i++)
            rsum[i] += __shfl_xor_sync(0xffffffffu, rsum[i], m);

    float inv[4];
    #pragma unroll
    for (int i = 0; i < 4; i++) inv[i] = 1.0f / rsum[i];

    if (tx == 0) {
        #pragma unroll
        for (int i = 0; i < 4; i++)
            g_inv[b * Ss + q0 + r0 + i] = inv[i];
    }

    // ---- normalized attn_vec ----
    float* Og = out_vec + ((size_t)(b * Ss + q0 + r0)) * Dh + c0;
    #pragma unroll
    for (int i = 0; i < 4; i++)
        *(float4*)(Og + (size_t)i * Dh) =
            make_float4(acc[i][0] * inv[i], acc[i][1] * inv[i],
                        acc[i][2] * inv[i], acc[i][3] * inv[i]);
}

// Scale written causal region by 1/rowsum; zero-fill beyond the written tiles.
__global__ __launch_bounds__(256)
void norm_w(float* __restrict__ w)
{
    const size_t idx = (size_t)blockIdx.x * 256 + threadIdx.x;   // float4 index
    const int    c4  = (int)(idx & (Ss / 4 - 1));
    const size_t row = idx >> 10;                // / (Ss/4)
    const int    q   = (int)(row & (Ss - 1));
    const int    k   = c4 << 2;

    float4 v = make_float4(0.f, 0.f, 0.f, 0.f);
    const int lim = ((q >> 6) + 1) << 6;         // written-columns limit for this row
    if (k < lim) {
        const float inv = g_inv[row];
        v = *(const float4*)(w + (idx << 2));    // masked entries are exact 0 already
        v.x *= inv; v.y *= inv; v.z *= inv; v.w *= inv;
    }
    *(float4*)(w + (idx << 2)) = v;
}

extern "C" void kernel_launch(void* const* d_in, const int* in_sizes, int n_in,
                              void* d_out, int out_size)
{
    const float* Q = (const float*)d_in[0];
    const float* K = (const float*)d_in[1];
    const float* V = (const float*)d_in[2];

    float* out_vec = (float*)d_out;
    float* out_w   = out_vec + (size_t)Bb * Ss * Dh;

    cudaFuncSetAttribute(attn_fwd, cudaFuncAttributeMaxDynamicSharedMemorySize,
                         SMEM_BYTES);

    dim3 grid(Ss / BQ, Bb);
    attn_fwd<<<grid, 256, SMEM_BYTES>>>(Q, K, V, out_vec, out_w);

    const size_t nvec4 = (size_t)Bb * Ss * Ss / 4;
    norm_w<<<(unsigned)(nvec4 / 256), 256>>>(out_w);
}

// round 2
// speedup vs baseline: 2.5247x; 2.5247x over previous
#include <cuda_runtime.h>
#include <cstdint>
#include <math.h>

// Causal attention, B=4, S=4096, D=64, fp32.
// out = [ attn_vec (B*S*64) | attn_weights (B*S*S) ]
//
// Phase A (attn_score): one CTA per causal 128x128 (qt,kt) tile pair.
//   QK^T via mma.sync tf32 with 2-term split (fp32-accurate), exp, write
//   unnormalized P to gmem, atomicAdd rowsums, PV partial via tf32 MMA,
//   atomicAdd into g_vec.
// Phase B (finalize): vec = g_vec / rowsum ; g_inv = 1/rowsum.
// Phase C (norm_w): rescale causal region of weights, zero-fill the rest.

constexpr int Bb = 4;
constexpr int Ss = 4096;
constexpr int Dh = 64;
constexpr int BQ = 128;
constexpr int BK = 128;

constexpr int LDQ = 68;    // Q/K smem row pitch (floats)
constexpr int LDV = 72;    // V smem row pitch
constexpr int LDP = 132;   // P smem row pitch

// smem layout (floats). Ps overlays the Q region after QK is done.
constexpr int OFF_QHI = 0;
constexpr int OFF_QLO = OFF_QHI + BQ * LDQ;        // 8704
constexpr int OFF_PS  = 0;                          // 128*132=16896 <= 17408
constexpr int OFF_KHI = OFF_QLO + BQ * LDQ;        // 17408
constexpr int OFF_KLO = OFF_KHI + BK * LDQ;        // 26112
constexpr int OFF_VS  = OFF_KLO + BK * LDQ;        // 34816
constexpr int SMEM_FLOATS = OFF_VS + BK * LDV;     // 44032
constexpr int SMEM_BYTES  = SMEM_FLOATS * 4;       // 176128

__device__ float g_rsum[Bb * Ss];
__device__ float g_inv [Bb * Ss];
__device__ float g_vec [Bb * Ss * Dh];

__device__ __forceinline__ unsigned f2tf(float x) {
    unsigned r;
    asm("cvt.rna.tf32.f32 %0, %1;" : "=r"(r) : "f"(x));
    return r;
}

__device__ __forceinline__ void mma8(float& c0, float& c1, float& c2, float& c3,
                                     unsigned a0, unsigned a1, unsigned a2, unsigned a3,
                                     unsigned b0, unsigned b1) {
    asm("mma.sync.aligned.m16n8k8.row.col.f32.tf32.tf32.f32 "
        "{%0,%1,%2,%3}, {%4,%5,%6,%7}, {%8,%9}, {%0,%1,%2,%3};"
        : "+f"(c0), "+f"(c1), "+f"(c2), "+f"(c3)
        : "r"(a0), "r"(a1), "r"(a2), "r"(a3), "r"(b0), "r"(b1));
}

__global__ __launch_bounds__(256, 1)
void attn_score(const float* __restrict__ Q, const float* __restrict__ K,
                const float* __restrict__ V, float* __restrict__ out_w)
{
    extern __shared__ float sm[];
    const int b = blockIdx.y;
    const int x = blockIdx.x;

    // invert triangular index: x -> (qt, kt), kt <= qt
    int qt = (int)((sqrtf(8.0f * (float)x + 1.0f) - 1.0f) * 0.5f);
    while ((qt + 1) * (qt + 2) / 2 <= x) qt++;
    while (qt * (qt + 1) / 2 > x) qt--;
    const int kt = x - qt * (qt + 1) / 2;
    const int q0 = qt * BQ, k0 = kt * BK;

    const int tid = threadIdx.x;

    // ---- load tiles; split Q,K into tf32 hi/lo; V natural ----
    const float* Qg = Q + ((size_t)(b * Ss + q0)) * Dh;
    const float* Kg = K + ((size_t)(b * Ss + k0)) * Dh;
    const float* Vg = V + ((size_t)(b * Ss + k0)) * Dh;
    #pragma unroll
    for (int i = 0; i < 8; i++) {
        const int idx = tid + i * 256;
        const int row = idx >> 4;
        const int c4  = (idx & 15) << 2;

        float4 q4 = *(const float4*)(Qg + row * Dh + c4);
        float4 qh, ql;
        qh.x = __uint_as_float(f2tf(q4.x)); ql.x = __uint_as_float(f2tf(q4.x - qh.x));
        qh.y = __uint_as_float(f2tf(q4.y)); ql.y = __uint_as_float(f2tf(q4.y - qh.y));
        qh.z = __uint_as_float(f2tf(q4.z)); ql.z = __uint_as_float(f2tf(q4.z - qh.z));
        qh.w = __uint_as_float(f2tf(q4.w)); ql.w = __uint_as_float(f2tf(q4.w - qh.w));
        *(float4*)(sm + OFF_QHI + row * LDQ + c4) = qh;
        *(float4*)(sm + OFF_QLO + row * LDQ + c4) = ql;

        float4 k4 = *(const float4*)(Kg + row * Dh + c4);
        float4 kh, kl;
        kh.x = __uint_as_float(f2tf(k4.x)); kl.x = __uint_as_float(f2tf(k4.x - kh.x));
        kh.y = __uint_as_float(f2tf(k4.y)); kl.y = __uint_as_float(f2tf(k4.y - kh.y));
        kh.z = __uint_as_float(f2tf(k4.z)); kl.z = __uint_as_float(f2tf(k4.z - kh.z));
        kh.w = __uint_as_float(f2tf(k4.w)); kl.w = __uint_as_float(f2tf(k4.w - kh.w));
        *(float4*)(sm + OFF_KHI + row * LDQ + c4) = kh;
        *(float4*)(sm + OFF_KLO + row * LDQ + c4) = kl;

        *(float4*)(sm + OFF_VS + row * LDV + c4) = *(const float4*)(Vg + row * Dh + c4);
    }
    __syncthreads();

    const int w = tid >> 5, lane = tid & 31;
    const int grp = lane >> 2, tig = lane & 3;

    // ---- QK^T: warp tile 64x32 (wm in {0,1}, wn in {0..3}) ----
    const int wm = w & 1, wn = w >> 1;
    float acc[4][4][4];
    #pragma unroll
    for (int i = 0; i < 4; i++)
        #pragma unroll
        for (int j = 0; j < 4; j++)
            #pragma unroll
            for (int c = 0; c < 4; c++) acc[i][j][c] = 0.0f;

    for (int kk = 0; kk < 8; kk++) {
        const int kb = kk * 8;
        unsigned ah[4][4], al[4][4];
        #pragma unroll
        for (int am = 0; am < 4; am++) {
            const int r = wm * 64 + am * 16 + grp;
            const float* ph = sm + OFF_QHI + r * LDQ + kb + tig;
            ah[am][0] = __float_as_uint(ph[0]);
            ah[am][1] = __float_as_uint(ph[8 * LDQ]);
            ah[am][2] = __float_as_uint(ph[4]);
            ah[am][3] = __float_as_uint(ph[8 * LDQ + 4]);
            const float* pl = sm + OFF_QLO + r * LDQ + kb + tig;
            al[am][0] = __float_as_uint(pl[0]);
            al[am][1] = __float_as_uint(pl[8 * LDQ]);
            al[am][2] = __float_as_uint(pl[4]);
            al[am][3] = __float_as_uint(pl[8 * LDQ + 4]);
        }
        unsigned bh[4][2], bl[4][2];
        #pragma unroll
        for (int an = 0; an < 4; an++) {
            const int c = wn * 32 + an * 8 + grp;
            const float* ph = sm + OFF_KHI + c * LDQ + kb + tig;
            bh[an][0] = __float_as_uint(ph[0]);
            bh[an][1] = __float_as_uint(ph[4]);
            const float* pl = sm + OFF_KLO + c * LDQ + kb + tig;
            bl[an][0] = __float_as_uint(pl[0]);
            bl[an][1] = __float_as_uint(pl[4]);
        }
        #pragma unroll
        for (int am = 0; am < 4; am++)
            #pragma unroll
            for (int an = 0; an < 4; an++) {
                float* c = acc[am][an];
                mma8(c[0], c[1], c[2], c[3], ah[am][0], ah[am][1], ah[am][2], ah[am][3], bh[an][0], bh[an][1]);
                mma8(c[0], c[1], c[2], c[3], ah[am][0], ah[am][1], ah[am][2], ah[am][3], bl[an][0], bl[an][1]);
                mma8(c[0], c[1], c[2], c[3], al[am][0], al[am][1], al[am][2], al[am][3], bh[an][0], bh[an][1]);
            }
    }

    __syncthreads();   // all smem QK reads done; Ps may overwrite Q region

    // ---- mask + exp, stage Ps, write unnormalized weights, rowsums ----
    #pragma unroll
    for (int am = 0; am < 4; am++) {
        const int rl_loc = wm * 64 + am * 16 + grp;     // tile-local row (low)
        const int rowl = q0 + rl_loc;
        const int rowh = rowl + 8;
        float rlo = 0.0f, rhi = 0.0f;
        #pragma unroll
        for (int an = 0; an < 4; an++) {
            const int cl_loc = wn * 32 + an * 8 + 2 * tig;
            const int col = k0 + cl_loc;
            float* c = acc[am][an];
            float e0 = (col     <= rowl) ? __expf(c[0] * 0.125f) : 0.0f;
            float e1 = (col + 1 <= rowl) ? __expf(c[1] * 0.125f) : 0.0f;
            float e2 = (col     <= rowh) ? __expf(c[2] * 0.125f) : 0.0f;
            float e3 = (col + 1 <= rowh) ? __expf(c[3] * 0.125f) : 0.0f;
            c[0] = e0; c[1] = e1; c[2] = e2; c[3] = e3;
            rlo += e0 + e1; rhi += e2 + e3;

            *(float2*)(sm + OFF_PS + rl_loc * LDP + cl_loc)       = make_float2(e0, e1);
            *(float2*)(sm + OFF_PS + (rl_loc + 8) * LDP + cl_loc) = make_float2(e2, e3);

            float* wg = out_w + ((size_t)(b * Ss + rowl)) * Ss + col;
            *(float2*)wg                    = make_float2(e0, e1);
            *(float2*)(wg + (size_t)8 * Ss) = make_float2(e2, e3);
        }
        rlo += __shfl_xor_sync(0xffffffffu, rlo, 1);
        rlo += __shfl_xor_sync(0xffffffffu, rlo, 2);
        rhi += __shfl_xor_sync(0xffffffffu, rhi, 1);
        rhi += __shfl_xor_sync(0xffffffffu, rhi, 2);
        if (tig == 0) {
            atomicAdd(&g_rsum[b * Ss + rowl], rlo);
            atomicAdd(&g_rsum[b * Ss + rowh], rhi);
        }
    }
    __syncthreads();   // Ps fully staged

    // ---- PV partial: warp tile 32x32 (wm2 in {0..3}, wn2 in {0,1}) ----
    const int wm2 = w >> 1, wn2 = w & 1;
    float vacc[2][4][4];
    #pragma unroll
    for (int i = 0; i < 2; i++)
        #pragma unroll
        for (int j = 0; j < 4; j++)
            #pragma unroll
            for (int c = 0; c < 4; c++) vacc[i][j][c] = 0.0f;

    for (int ks = 0; ks < 16; ks++) {
        const int kb = ks * 8;
        unsigned pa[2][4];
        #pragma unroll
        for (int am = 0; am < 2; am++) {
            const int r = wm2 * 32 + am * 16 + grp;
            const float* p = sm + OFF_PS + r * LDP + kb + tig;
            pa[am][0] = f2tf(p[0]);
            pa[am][1] = f2tf(p[8 * LDP]);
            pa[am][2] = f2tf(p[4]);
            pa[am][3] = f2tf(p[8 * LDP + 4]);
        }
        unsigned vb[4][2];
        #pragma unroll
        for (int an = 0; an < 4; an++) {
            const int c = wn2 * 32 + an * 8 + grp;
            const float* p = sm + OFF_VS + (kb + tig) * LDV + c;
            vb[an][0] = f2tf(p[0]);
            vb[an][1] = f2tf(p[4 * LDV]);
        }
        #pragma unroll
        for (int am = 0; am < 2; am++)
            #pragma unroll
            for (int an = 0; an < 4; an++) {
                float* c = vacc[am][an];
                mma8(c[0], c[1], c[2], c[3], pa[am][0], pa[am][1], pa[am][2], pa[am][3], vb[an][0], vb[an][1]);
            }
    }

    #pragma unroll
    for (int am = 0; am < 2; am++) {
        const int gl = b * Ss + q0 + wm2 * 32 + am * 16 + grp;  // global row (low)
        const int gh = gl + 8;
        #pragma unroll
        for (int an = 0; an < 4; an++) {
            const int col = wn2 * 32 + an * 8 + 2 * tig;
            float* c = vacc[am][an];
            atomicAdd(&g_vec[(size_t)gl * Dh + col],     c[0]);
            atomicAdd(&g_vec[(size_t)gl * Dh + col + 1], c[1]);
            atomicAdd(&g_vec[(size_t)gh * Dh + col],     c[2]);
            atomicAdd(&g_vec[(size_t)gh * Dh + col + 1], c[3]);
        }
    }
}

// vec = g_vec / rowsum ; also publish g_inv
__global__ __launch_bounds__(256)
void finalize(float* __restrict__ out_vec)
{
    const int idx = blockIdx.x * 256 + threadIdx.x;   // 262144 threads
    const int row = idx >> 4;
    const int c4  = (idx & 15) << 2;
    const float inv = 1.0f / g_rsum[row];
    if ((idx & 15) == 0) g_inv[row] = inv;
    float4 v = *(const float4*)(g_vec + (size_t)row * Dh + c4);
    v.x *= inv; v.y *= inv; v.z *= inv; v.w *= inv;
    *(float4*)(out_vec + (size_t)row * Dh + c4) = v;
}

// Scale written causal region by 1/rowsum; zero-fill beyond written tiles.
__global__ __launch_bounds__(256)
void norm_w(float* __restrict__ w)
{
    const size_t idx = (size_t)blockIdx.x * 256 + threadIdx.x;   // float4 index
    const int    c4  = (int)(idx & (Ss / 4 - 1));
    const size_t row = idx >> 10;
    const int    q   = (int)(row & (Ss - 1));
    const int    k   = c4 << 2;

    float4 v = make_float4(0.f, 0.f, 0.f, 0.f);
    const int lim = ((q >> 7) + 1) << 7;          // BQ=128 tile granularity
    if (k < lim) {
        const float inv = g_inv[row];
        v = *(const float4*)(w + (idx << 2));
        v.x *= inv; v.y *= inv; v.z *= inv; v.w *= inv;
    }
    *(float4*)(w + (idx << 2)) = v;
}

extern "C" void kernel_launch(void* const* d_in, const int* in_sizes, int n_in,
                              void* d_out, int out_size)
{
    const float* Q = (const float*)d_in[0];
    const float* K = (const float*)d_in[1];
    const float* V = (const float*)d_in[2];

    float* out_vec = (float*)d_out;
    float* out_w   = out_vec + (size_t)Bb * Ss * Dh;

    void* p_rsum = nullptr;
    void* p_vec  = nullptr;
    cudaGetSymbolAddress(&p_rsum, g_rsum);
    cudaGetSymbolAddress(&p_vec,  g_vec);
    cudaMemsetAsync(p_rsum, 0, sizeof(float) * Bb * Ss);
    cudaMemsetAsync(p_vec,  0, sizeof(float) * Bb * Ss * Dh);

    cudaFuncSetAttribute(attn_score, cudaFuncAttributeMaxDynamicSharedMemorySize,
                         SMEM_BYTES);

    const int npairs = (Ss / BQ) * (Ss / BQ + 1) / 2;   // 528
    dim3 gridA(npairs, Bb);
    attn_score<<<gridA, 256, SMEM_BYTES>>>(Q, K, V, out_w);

    finalize<<<(Bb * Ss * Dh / 4) / 256, 256>>>(out_vec);

    const size_t nvec4 = (size_t)Bb * Ss * Ss / 4;
    norm_w<<<(unsigned)(nvec4 / 256), 256>>>(out_w);
}

// round 3
// speedup vs baseline: 2.7186x; 1.0768x over previous
#include <cuda_runtime.h>
#include <cstdint>
#include <math.h>

// Causal attention, B=4, S=4096, D=64, fp32.
// out = [ attn_vec (B*S*64) | attn_weights (B*S*S) ]

constexpr int Bb = 4;
constexpr int Ss = 4096;
constexpr int Dh = 64;
constexpr int BQ = 128;
constexpr int BK = 128;

constexpr int LDQ = 68;    // Q/K smem row pitch (floats)
constexpr int LDP = 132;   // P smem row pitch

// smem layout (floats). Ps overlays Q+K after QK is done. V is swizzled, pitch 64.
constexpr int OFF_Q = 0;
constexpr int OFF_K = OFF_Q + BQ * LDQ;          // 8704
constexpr int OFF_PS = 0;                         // 128*132=16896 <= 17408 (Q+K)
constexpr int OFF_V = OFF_K + BK * LDQ;          // 17408
constexpr int SMEM_FLOATS = OFF_V + BK * 64;     // 25600
constexpr int SMEM_BYTES  = SMEM_FLOATS * 4;     // 102400

__device__ float g_rsum[Bb * Ss];
__device__ float g_inv [Bb * Ss];
__device__ float g_vec [Bb * Ss * Dh];

__device__ __forceinline__ unsigned f2tf(float x) {
    unsigned r;
    asm("cvt.rna.tf32.f32 %0, %1;" : "=r"(r) : "f"(x));
    return r;
}

__device__ __forceinline__ void mma8(float& c0, float& c1, float& c2, float& c3,
                                     unsigned a0, unsigned a1, unsigned a2, unsigned a3,
                                     unsigned b0, unsigned b1) {
    asm("mma.sync.aligned.m16n8k8.row.col.f32.tf32.tf32.f32 "
        "{%0,%1,%2,%3}, {%4,%5,%6,%7}, {%8,%9}, {%0,%1,%2,%3};"
        : "+f"(c0), "+f"(c1), "+f"(c2), "+f"(c3)
        : "r"(a0), "r"(a1), "r"(a2), "r"(a3), "r"(b0), "r"(b1));
}

__device__ __forceinline__ void cpa16(uint32_t dst, const void* src) {
    asm volatile("cp.async.ca.shared.global [%0], [%1], 16;" :: "r"(dst), "l"(src));
}

// swizzled V column: permute 8-float blocks by row&7
__device__ __forceinline__ int vswz(int row, int col) {
    return ((((col >> 3) ^ (row & 7)) << 3) | (col & 7));
}

__global__ __launch_bounds__(256, 2)
void attn_score(const float* __restrict__ Q, const float* __restrict__ K,
                const float* __restrict__ V, float* __restrict__ out_w)
{
    extern __shared__ float sm[];
    const int b = blockIdx.y;
    const int x = blockIdx.x;

    // invert triangular index: x -> (qt, kt), kt <= qt
    int qt = (int)((sqrtf(8.0f * (float)x + 1.0f) - 1.0f) * 0.5f);
    while ((qt + 1) * (qt + 2) / 2 <= x) qt++;
    while (qt * (qt + 1) / 2 > x) qt--;
    const int kt = x - qt * (qt + 1) / 2;
    const int q0 = qt * BQ, k0 = kt * BK;

    const int tid = threadIdx.x;
    const uint32_t smb = (uint32_t)__cvta_generic_to_shared(sm);

    // ---- async-load Q, K (natural, pitch 68) and V (swizzled, pitch 64) ----
    const float* Qg = Q + ((size_t)(b * Ss + q0)) * Dh;
    const float* Kg = K + ((size_t)(b * Ss + k0)) * Dh;
    const float* Vg = V + ((size_t)(b * Ss + k0)) * Dh;
    #pragma unroll
    for (int i = 0; i < 8; i++) {
        const int idx = tid + i * 256;
        const int row = idx >> 4;
        const int c4  = (idx & 15) << 2;
        cpa16(smb + (OFF_Q + row * LDQ + c4) * 4, Qg + row * Dh + c4);
        cpa16(smb + (OFF_K + row * LDQ + c4) * 4, Kg + row * Dh + c4);
        cpa16(smb + (OFF_V + row * 64 + vswz(row, c4)) * 4, Vg + row * Dh + c4);
    }
    asm volatile("cp.async.commit_group;");
    asm volatile("cp.async.wait_group 0;");
    __syncthreads();

    const int w = tid >> 5, lane = tid & 31;
    const int grp = lane >> 2, tig = lane & 3;

    // ---- QK^T: warp tile 64x32 (wm in {0,1}, wn in {0..3}) ----
    const int wm = w & 1, wn = w >> 1;
    float acc[4][4][4];
    #pragma unroll
    for (int i = 0; i < 4; i++)
        #pragma unroll
        for (int j = 0; j < 4; j++)
            #pragma unroll
            for (int c = 0; c < 4; c++) acc[i][j][c] = 0.0f;

    for (int kk = 0; kk < 8; kk++) {
        const int kb = kk * 8;
        unsigned ah[4][4], al[4][4];
        #pragma unroll
        for (int am = 0; am < 4; am++) {
            const int r = wm * 64 + am * 16 + grp;
            const float* p = sm + OFF_Q + r * LDQ + kb + tig;
            float v0 = p[0], v1 = p[8 * LDQ], v2 = p[4], v3 = p[8 * LDQ + 4];
            ah[am][0] = f2tf(v0); al[am][0] = f2tf(v0 - __uint_as_float(ah[am][0]));
            ah[am][1] = f2tf(v1); al[am][1] = f2tf(v1 - __uint_as_float(ah[am][1]));
            ah[am][2] = f2tf(v2); al[am][2] = f2tf(v2 - __uint_as_float(ah[am][2]));
            ah[am][3] = f2tf(v3); al[am][3] = f2tf(v3 - __uint_as_float(ah[am][3]));
        }
        unsigned bh[4][2], bl[4][2];
        #pragma unroll
        for (int an = 0; an < 4; an++) {
            const int c = wn * 32 + an * 8 + grp;
            const float* p = sm + OFF_K + c * LDQ + kb + tig;
            float v0 = p[0], v1 = p[4];
            bh[an][0] = f2tf(v0); bl[an][0] = f2tf(v0 - __uint_as_float(bh[an][0]));
            bh[an][1] = f2tf(v1); bl[an][1] = f2tf(v1 - __uint_as_float(bh[an][1]));
        }
        #pragma unroll
        for (int am = 0; am < 4; am++)
            #pragma unroll
            for (int an = 0; an < 4; an++) {
                float* c = acc[am][an];
                mma8(c[0], c[1], c[2], c[3], ah[am][0], ah[am][1], ah[am][2], ah[am][3], bh[an][0], bh[an][1]);
                mma8(c[0], c[1], c[2], c[3], ah[am][0], ah[am][1], ah[am][2], ah[am][3], bl[an][0], bl[an][1]);
                mma8(c[0], c[1], c[2], c[3], al[am][0], al[am][1], al[am][2], al[am][3], bh[an][0], bh[an][1]);
            }
    }

    __syncthreads();   // all smem QK reads done; Ps may overwrite Q+K region

    // ---- mask + exp, stage Ps, write unnormalized weights, rowsums ----
    #pragma unroll
    for (int am = 0; am < 4; am++) {
        const int rl_loc = wm * 64 + am * 16 + grp;     // tile-local row (low)
        const int rowl = q0 + rl_loc;
        const int rowh = rowl + 8;
        float rlo = 0.0f, rhi = 0.0f;
        #pragma unroll
        for (int an = 0; an < 4; an++) {
            const int cl_loc = wn * 32 + an * 8 + 2 * tig;
            const int col = k0 + cl_loc;
            float* c = acc[am][an];
            float e0 = (col     <= rowl) ? __expf(c[0] * 0.125f) : 0.0f;
            float e1 = (col + 1 <= rowl) ? __expf(c[1] * 0.125f) : 0.0f;
            float e2 = (col     <= rowh) ? __expf(c[2] * 0.125f) : 0.0f;
            float e3 = (col + 1 <= rowh) ? __expf(c[3] * 0.125f) : 0.0f;
            rlo += e0 + e1; rhi += e2 + e3;

            *(float2*)(sm + OFF_PS + rl_loc * LDP + cl_loc)       = make_float2(e0, e1);
            *(float2*)(sm + OFF_PS + (rl_loc + 8) * LDP + cl_loc) = make_float2(e2, e3);

            float* wg = out_w + ((size_t)(b * Ss + rowl)) * Ss + col;
            *(float2*)wg                    = make_float2(e0, e1);
            *(float2*)(wg + (size_t)8 * Ss) = make_float2(e2, e3);
        }
        rlo += __shfl_xor_sync(0xffffffffu, rlo, 1);
        rlo += __shfl_xor_sync(0xffffffffu, rlo, 2);
        rhi += __shfl_xor_sync(0xffffffffu, rhi, 1);
        rhi += __shfl_xor_sync(0xffffffffu, rhi, 2);
        if (tig == 0) {
            atomicAdd(&g_rsum[b * Ss + rowl], rlo);
            atomicAdd(&g_rsum[b * Ss + rowh], rhi);
        }
    }
    __syncthreads();   // Ps fully staged

    // ---- PV partial: warp tile 32x32 (wm2 in {0..3}, wn2 in {0,1}) ----
    const int wm2 = w >> 1, wn2 = w & 1;
    float vacc[2][4][4];
    #pragma unroll
    for (int i = 0; i < 2; i++)
        #pragma unroll
        for (int j = 0; j < 4; j++)
            #pragma unroll
            for (int c = 0; c < 4; c++) vacc[i][j][c] = 0.0f;

    for (int ks = 0; ks < 16; ks++) {
        const int kb = ks * 8;
        unsigned pa[2][4];
        #pragma unroll
        for (int am = 0; am < 2; am++) {
            const int r = wm2 * 32 + am * 16 + grp;
            const float* p = sm + OFF_PS + r * LDP + kb + tig;
            pa[am][0] = f2tf(p[0]);
            pa[am][1] = f2tf(p[8 * LDP]);
            pa[am][2] = f2tf(p[4]);
            pa[am][3] = f2tf(p[8 * LDP + 4]);
        }
        unsigned vb[4][2];
        #pragma unroll
        for (int an = 0; an < 4; an++) {
            const int c = wn2 * 32 + an * 8 + grp;
            const int r0v = kb + tig, r1v = kb + tig + 4;
            vb[an][0] = f2tf(sm[OFF_V + r0v * 64 + vswz(r0v, c)]);
            vb[an][1] = f2tf(sm[OFF_V + r1v * 64 + vswz(r1v, c)]);
        }
        #pragma unroll
        for (int am = 0; am < 2; am++)
            #pragma unroll
            for (int an = 0; an < 4; an++) {
                float* c = vacc[am][an];
                mma8(c[0], c[1], c[2], c[3], pa[am][0], pa[am][1], pa[am][2], pa[am][3], vb[an][0], vb[an][1]);
            }
    }

    #pragma unroll
    for (int am = 0; am < 2; am++) {
        const int gl = b * Ss + q0 + wm2 * 32 + am * 16 + grp;  // global row (low)
        const int gh = gl + 8;
        #pragma unroll
        for (int an = 0; an < 4; an++) {
            const int col = wn2 * 32 + an * 8 + 2 * tig;
            float* c = vacc[am][an];
            atomicAdd(&g_vec[(size_t)gl * Dh + col],     c[0]);
            atomicAdd(&g_vec[(size_t)gl * Dh + col + 1], c[1]);
            atomicAdd(&g_vec[(size_t)gh * Dh + col],     c[2]);
            atomicAdd(&g_vec[(size_t)gh * Dh + col + 1], c[3]);
        }
    }
}

// vec = g_vec / rowsum ; also publish g_inv
__global__ __launch_bounds__(256)
void finalize(float* __restrict__ out_vec)
{
    const int idx = blockIdx.x * 256 + threadIdx.x;
    const int row = idx >> 4;
    const int c4  = (idx & 15) << 2;
    const float inv = 1.0f / g_rsum[row];
    if ((idx & 15) == 0) g_inv[row] = inv;
    float4 v = *(const float4*)(g_vec + (size_t)row * Dh + c4);
    v.x *= inv; v.y *= inv; v.z *= inv; v.w *= inv;
    *(float4*)(out_vec + (size_t)row * Dh + c4) = v;
}

// Scale written causal region by 1/rowsum; zero-fill beyond written tiles.
__global__ __launch_bounds__(256)
void norm_w(float* __restrict__ w)
{
    const size_t idx = (size_t)blockIdx.x * 256 + threadIdx.x;   // float4 index
    const int    c4  = (int)(idx & (Ss / 4 - 1));
    const size_t row = idx >> 10;
    const int    q   = (int)(row & (Ss - 1));
    const int    k   = c4 << 2;

    float4 v = make_float4(0.f, 0.f, 0.f, 0.f);
    const int lim = ((q >> 7) + 1) << 7;          // BQ=128 tile granularity
    if (k < lim) {
        const float inv = g_inv[row];
        v = *(const float4*)(w + (idx << 2));
        v.x *= inv; v.y *= inv; v.z *= inv; v.w *= inv;
    }
    *(float4*)(w + (idx << 2)) = v;
}

extern "C" void kernel_launch(void* const* d_in, const int* in_sizes, int n_in,
                              void* d_out, int out_size)
{
    const float* Q = (const float*)d_in[0];
    const float* K = (const float*)d_in[1];
    const float* V = (const float*)d_in[2];

    float* out_vec = (float*)d_out;
    float* out_w   = out_vec + (size_t)Bb * Ss * Dh;

    void* p_rsum = nullptr;
    void* p_vec  = nullptr;
    cudaGetSymbolAddress(&p_rsum, g_rsum);
    cudaGetSymbolAddress(&p_vec,  g_vec);
    cudaMemsetAsync(p_rsum, 0, sizeof(float) * Bb * Ss);
    cudaMemsetAsync(p_vec,  0, sizeof(float) * Bb * Ss * Dh);

    cudaFuncSetAttribute(attn_score, cudaFuncAttributeMaxDynamicSharedMemorySize,
                         SMEM_BYTES);

    const int npairs = (Ss / BQ) * (Ss / BQ + 1) / 2;   // 528
    dim3 gridA(npairs, Bb);
    attn_score<<<gridA, 256, SMEM_BYTES>>>(Q, K, V, out_w);

    finalize<<<(Bb * Ss * Dh / 4) / 256, 256>>>(out_vec);

    const size_t nvec4 = (size_t)Bb * Ss * Ss / 4;
    norm_w<<<(unsigned)(nvec4 / 256), 256>>>(out_w);
}

// round 4
// speedup vs baseline: 2.7568x; 1.0141x over previous
#include <cuda_runtime.h>
#include <cstdint>
#include <math.h>

// Causal attention, B=4, S=4096, D=64, fp32.
// out = [ attn_vec (B*S*64) | attn_weights (B*S*S) ]

constexpr int Bb = 4;
constexpr int Ss = 4096;
constexpr int Dh = 64;
constexpr int BQ = 128;
constexpr int BK = 128;
constexpr int NT = Ss / BQ;          // 32 tiles per side

constexpr int LDQ = 68;    // Q/K smem row pitch (floats)
constexpr int LDP = 132;   // P smem row pitch

constexpr int OFF_Q = 0;
constexpr int OFF_K = OFF_Q + BQ * LDQ;          // 8704
constexpr int OFF_PS = 0;                         // P overlays Q+K (16896 <= 17408)
constexpr int OFF_V = OFF_K + BK * LDQ;          // 17408
constexpr int SMEM_FLOATS = OFF_V + BK * 64;     // 25600
constexpr int SMEM_BYTES  = SMEM_FLOATS * 4;     // 102400

__device__ float g_rsum[Bb * Ss];
__device__ float g_inv [Bb * Ss];
__device__ float g_vec [Bb * Ss * Dh];

__device__ __forceinline__ unsigned f2tf(float x) {
    unsigned r;
    asm("cvt.rna.tf32.f32 %0, %1;" : "=r"(r) : "f"(x));
    return r;
}

__device__ __forceinline__ void mma8(float& c0, float& c1, float& c2, float& c3,
                                     unsigned a0, unsigned a1, unsigned a2, unsigned a3,
                                     unsigned b0, unsigned b1) {
    asm("mma.sync.aligned.m16n8k8.row.col.f32.tf32.tf32.f32 "
        "{%0,%1,%2,%3}, {%4,%5,%6,%7}, {%8,%9}, {%0,%1,%2,%3};"
        : "+f"(c0), "+f"(c1), "+f"(c2), "+f"(c3)
        : "r"(a0), "r"(a1), "r"(a2), "r"(a3), "r"(b0), "r"(b1));
}

__device__ __forceinline__ void cpa16(uint32_t dst, const void* src) {
    asm volatile("cp.async.ca.shared.global [%0], [%1], 16;" :: "r"(dst), "l"(src));
}

// swizzled V column: permute 8-float blocks by row&7
__device__ __forceinline__ int vswz(int row, int col) {
    return ((((col >> 3) ^ (row & 7)) << 3) | (col & 7));
}

__global__ __launch_bounds__(256, 2)
void attn_score(const float* __restrict__ Q, const float* __restrict__ K,
                const float* __restrict__ V, float* __restrict__ out_w)
{
    extern __shared__ float sm[];
    const int b  = blockIdx.y;
    const int x  = blockIdx.x;
    const int qt = x >> 5;          // x / NT
    const int kt = x & (NT - 1);
    const int q0 = qt * BQ, k0 = kt * BK;
    const int tid = threadIdx.x;

    if (kt > qt) {
        // strictly-upper tile: pure zero-fill of the weights region, then exit
        float* wg = out_w + ((size_t)(b * Ss + q0)) * Ss + k0;
        const float4 z = make_float4(0.f, 0.f, 0.f, 0.f);
        #pragma unroll
        for (int i = 0; i < 16; i++) {
            const int idx = tid + i * 256;
            const int row = idx >> 5;
            const int c4  = (idx & 31) << 2;
            *(float4*)(wg + (size_t)row * Ss + c4) = z;
        }
        return;
    }

    const uint32_t smb = (uint32_t)__cvta_generic_to_shared(sm);

    // ---- async-load Q, K (natural, pitch 68) and V (swizzled, pitch 64) ----
    const float* Qg = Q + ((size_t)(b * Ss + q0)) * Dh;
    const float* Kg = K + ((size_t)(b * Ss + k0)) * Dh;
    const float* Vg = V + ((size_t)(b * Ss + k0)) * Dh;
    #pragma unroll
    for (int i = 0; i < 8; i++) {
        const int idx = tid + i * 256;
        const int row = idx >> 4;
        const int c4  = (idx & 15) << 2;
        cpa16(smb + (OFF_Q + row * LDQ + c4) * 4, Qg + row * Dh + c4);
        cpa16(smb + (OFF_K + row * LDQ + c4) * 4, Kg + row * Dh + c4);
        cpa16(smb + (OFF_V + row * 64 + vswz(row, c4)) * 4, Vg + row * Dh + c4);
    }
    asm volatile("cp.async.commit_group;");
    asm volatile("cp.async.wait_group 0;");
    __syncthreads();

    const int w = tid >> 5, lane = tid & 31;
    const int grp = lane >> 2, tig = lane & 3;

    // ---- QK^T: warp tile 64x32 (wm in {0,1}, wn in {0..3}) ----
    const int wm = w & 1, wn = w >> 1;
    float acc[4][4][4];
    #pragma unroll
    for (int i = 0; i < 4; i++)
        #pragma unroll
        for (int j = 0; j < 4; j++)
            #pragma unroll
            for (int c = 0; c < 4; c++) acc[i][j][c] = 0.0f;

    for (int kk = 0; kk < 8; kk++) {
        const int kb = kk * 8;
        unsigned ah[4][4], al[4][4];
        #pragma unroll
        for (int am = 0; am < 4; am++) {
            const int r = wm * 64 + am * 16 + grp;
            const float* p = sm + OFF_Q + r * LDQ + kb + tig;
            float v0 = p[0], v1 = p[8 * LDQ], v2 = p[4], v3 = p[8 * LDQ + 4];
            ah[am][0] = f2tf(v0); al[am][0] = f2tf(v0 - __uint_as_float(ah[am][0]));
            ah[am][1] = f2tf(v1); al[am][1] = f2tf(v1 - __uint_as_float(ah[am][1]));
            ah[am][2] = f2tf(v2); al[am][2] = f2tf(v2 - __uint_as_float(ah[am][2]));
            ah[am][3] = f2tf(v3); al[am][3] = f2tf(v3 - __uint_as_float(ah[am][3]));
        }
        unsigned bh[4][2], bl[4][2];
        #pragma unroll
        for (int an = 0; an < 4; an++) {
            const int c = wn * 32 + an * 8 + grp;
            const float* p = sm + OFF_K + c * LDQ + kb + tig;
            float v0 = p[0], v1 = p[4];
            bh[an][0] = f2tf(v0); bl[an][0] = f2tf(v0 - __uint_as_float(bh[an][0]));
            bh[an][1] = f2tf(v1); bl[an][1] = f2tf(v1 - __uint_as_float(bh[an][1]));
        }
        #pragma unroll
        for (int am = 0; am < 4; am++)
            #pragma unroll
            for (int an = 0; an < 4; an++) {
                float* c = acc[am][an];
                mma8(c[0], c[1], c[2], c[3], ah[am][0], ah[am][1], ah[am][2], ah[am][3], bh[an][0], bh[an][1]);
                mma8(c[0], c[1], c[2], c[3], ah[am][0], ah[am][1], ah[am][2], ah[am][3], bl[an][0], bl[an][1]);
                mma8(c[0], c[1], c[2], c[3], al[am][0], al[am][1], al[am][2], al[am][3], bh[an][0], bh[an][1]);
            }
    }

    __syncthreads();   // all smem QK reads done; Ps may overwrite Q+K region

    // ---- mask + exp, stage Ps, write unnormalized weights, rowsums ----
    #pragma unroll
    for (int am = 0; am < 4; am++) {
        const int rl_loc = wm * 64 + am * 16 + grp;
        const int rowl = q0 + rl_loc;
        const int rowh = rowl + 8;
        float rlo = 0.0f, rhi = 0.0f;
        #pragma unroll
        for (int an = 0; an < 4; an++) {
            const int cl_loc = wn * 32 + an * 8 + 2 * tig;
            const int col = k0 + cl_loc;
            float* c = acc[am][an];
            float e0 = (col     <= rowl) ? __expf(c[0] * 0.125f) : 0.0f;
            float e1 = (col + 1 <= rowl) ? __expf(c[1] * 0.125f) : 0.0f;
            float e2 = (col     <= rowh) ? __expf(c[2] * 0.125f) : 0.0f;
            float e3 = (col + 1 <= rowh) ? __expf(c[3] * 0.125f) : 0.0f;
            rlo += e0 + e1; rhi += e2 + e3;

            *(float2*)(sm + OFF_PS + rl_loc * LDP + cl_loc)       = make_float2(e0, e1);
            *(float2*)(sm + OFF_PS + (rl_loc + 8) * LDP + cl_loc) = make_float2(e2, e3);

            float* wg = out_w + ((size_t)(b * Ss + rowl)) * Ss + col;
            *(float2*)wg                    = make_float2(e0, e1);
            *(float2*)(wg + (size_t)8 * Ss) = make_float2(e2, e3);
        }
        rlo += __shfl_xor_sync(0xffffffffu, rlo, 1);
        rlo += __shfl_xor_sync(0xffffffffu, rlo, 2);
        rhi += __shfl_xor_sync(0xffffffffu, rhi, 1);
        rhi += __shfl_xor_sync(0xffffffffu, rhi, 2);
        if (tig == 0) {
            atomicAdd(&g_rsum[b * Ss + rowl], rlo);
            atomicAdd(&g_rsum[b * Ss + rowh], rhi);
        }
    }
    __syncthreads();   // Ps fully staged

    // ---- PV partial: warp tile 32x32 (wm2 in {0..3}, wn2 in {0,1}) ----
    const int wm2 = w >> 1, wn2 = w & 1;
    float vacc[2][4][4];
    #pragma unroll
    for (int i = 0; i < 2; i++)
        #pragma unroll
        for (int j = 0; j < 4; j++)
            #pragma unroll
            for (int c = 0; c < 4; c++) vacc[i][j][c] = 0.0f;

    for (int ks = 0; ks < 16; ks++) {
        const int kb = ks * 8;
        unsigned pa[2][4];
        #pragma unroll
        for (int am = 0; am < 2; am++) {
            const int r = wm2 * 32 + am * 16 + grp;
            const float* p = sm + OFF_PS + r * LDP + kb + tig;
            pa[am][0] = f2tf(p[0]);
            pa[am][1] = f2tf(p[8 * LDP]);
            pa[am][2] = f2tf(p[4]);
            pa[am][3] = f2tf(p[8 * LDP + 4]);
        }
        unsigned vb[4][2];
        #pragma unroll
        for (int an = 0; an < 4; an++) {
            const int c = wn2 * 32 + an * 8 + grp;
            const int r0v = kb + tig, r1v = kb + tig + 4;
            vb[an][0] = f2tf(sm[OFF_V + r0v * 64 + vswz(r0v, c)]);
            vb[an][1] = f2tf(sm[OFF_V + r1v * 64 + vswz(r1v, c)]);
        }
        #pragma unroll
        for (int am = 0; am < 2; am++)
            #pragma unroll
            for (int an = 0; an < 4; an++) {
                float* c = vacc[am][an];
                mma8(c[0], c[1], c[2], c[3], pa[am][0], pa[am][1], pa[am][2], pa[am][3], vb[an][0], vb[an][1]);
            }
    }

    #pragma unroll
    for (int am = 0; am < 2; am++) {
        const int gl = b * Ss + q0 + wm2 * 32 + am * 16 + grp;
        const int gh = gl + 8;
        #pragma unroll
        for (int an = 0; an < 4; an++) {
            const int col = wn2 * 32 + an * 8 + 2 * tig;
            float* c = vacc[am][an];
            atomicAdd(&g_vec[(size_t)gl * Dh + col],     c[0]);
            atomicAdd(&g_vec[(size_t)gl * Dh + col + 1], c[1]);
            atomicAdd(&g_vec[(size_t)gh * Dh + col],     c[2]);
            atomicAdd(&g_vec[(size_t)gh * Dh + col + 1], c[3]);
        }
    }
}

// vec = g_vec / rowsum ; also publish g_inv
__global__ __launch_bounds__(256)
void finalize(float* __restrict__ out_vec)
{
    const int idx = blockIdx.x * 256 + threadIdx.x;
    const int row = idx >> 4;
    const int c4  = (idx & 15) << 2;
    const float inv = 1.0f / g_rsum[row];
    if ((idx & 15) == 0) g_inv[row] = inv;
    float4 v = *(const float4*)(g_vec + (size_t)row * Dh + c4);
    v.x *= inv; v.y *= inv; v.z *= inv; v.w *= inv;
    *(float4*)(out_vec + (size_t)row * Dh + c4) = v;
}

// Scale causal tiles by 1/rowsum (tile-parallel; only kt<=qt tiles exist here).
__global__ __launch_bounds__(256)
void norm_w(float* __restrict__ w)
{
    const int b = blockIdx.y;
    const int x = blockIdx.x;

    // invert triangular index: x -> (qt, kt), kt <= qt
    int qt = (int)((sqrtf(8.0f * (float)x + 1.0f) - 1.0f) * 0.5f);
    while ((qt + 1) * (qt + 2) / 2 <= x) qt++;
    while (qt * (qt + 1) / 2 > x) qt--;
    const int kt = x - qt * (qt + 1) / 2;

    const int tid = threadIdx.x;
    float* wg = w + ((size_t)(b * Ss + qt * BQ)) * Ss + kt * BK;
    const float* invp = g_inv + b * Ss + qt * BQ;

    #pragma unroll
    for (int i = 0; i < 16; i++) {
        const int idx = tid + i * 256;
        const int row = idx >> 5;
        const int c4  = (idx & 31) << 2;
        const float inv = invp[row];
        float4 v = *(const float4*)(wg + (size_t)row * Ss + c4);
        v.x *= inv; v.y *= inv; v.z *= inv; v.w *= inv;
        *(float4*)(wg + (size_t)row * Ss + c4) = v;
    }
}

extern "C" void kernel_launch(void* const* d_in, const int* in_sizes, int n_in,
                              void* d_out, int out_size)
{
    const float* Q = (const float*)d_in[0];
    const float* K = (const float*)d_in[1];
    const float* V = (const float*)d_in[2];

    float* out_vec = (float*)d_out;
    float* out_w   = out_vec + (size_t)Bb * Ss * Dh;

    void* p_rsum = nullptr;
    void* p_vec  = nullptr;
    cudaGetSymbolAddress(&p_rsum, g_rsum);
    cudaGetSymbolAddress(&p_vec,  g_vec);
    cudaMemsetAsync(p_rsum, 0, sizeof(float) * Bb * Ss);
    cudaMemsetAsync(p_vec,  0, sizeof(float) * Bb * Ss * Dh);

    cudaFuncSetAttribute(attn_score, cudaFuncAttributeMaxDynamicSharedMemorySize,
                         SMEM_BYTES);

    dim3 gridA(NT * NT, Bb);                       // all (qt,kt); upper tiles zero-fill
    attn_score<<<gridA, 256, SMEM_BYTES>>>(Q, K, V, out_w);

    finalize<<<(Bb * Ss * Dh / 4) / 256, 256>>>(out_vec);

    const int ncausal = NT * (NT + 1) / 2;         // 528
    dim3 gridN(ncausal, Bb);
    norm_w<<<gridN, 256>>>(out_w);
}

// round 5
// speedup vs baseline: 3.3686x; 1.2219x over previous
#include <cuda_runtime.h>
#include <cstdint>
#include <math.h>

// Causal attention, B=4, S=4096, D=64, fp32.
// out = [ attn_vec (B*S*64) | attn_weights (B*S*S) ]
// Q/K/V/P live in smem as tf32 bit patterns; mainloops are pure LDS+MMA.

constexpr int Bb = 4;
constexpr int Ss = 4096;
constexpr int Dh = 64;
constexpr int BQ = 128;
constexpr int BK = 128;
constexpr int NT = Ss / BQ;          // 32 tiles per side

constexpr int LDQ = 68;    // Q/K smem row pitch (floats)
constexpr int LDP = 132;   // P smem row pitch

constexpr int OFF_Q = 0;
constexpr int OFF_K = OFF_Q + BQ * LDQ;          // 8704
constexpr int OFF_PS = 0;                         // P overlays Q+K (16896 <= 17408)
constexpr int OFF_V = OFF_K + BK * LDQ;          // 17408
constexpr int SMEM_FLOATS = OFF_V + BK * 64;     // 25600
constexpr int SMEM_BYTES  = SMEM_FLOATS * 4;     // 102400

__device__ float g_rsum[Bb * Ss];
__device__ float g_inv [Bb * Ss];
__device__ float g_vec [Bb * Ss * Dh];

__device__ __forceinline__ unsigned f2tf(float x) {
    unsigned r;
    asm("cvt.rna.tf32.f32 %0, %1;" : "=r"(r) : "f"(x));
    return r;
}

__device__ __forceinline__ void mma8(float& c0, float& c1, float& c2, float& c3,
                                     unsigned a0, unsigned a1, unsigned a2, unsigned a3,
                                     unsigned b0, unsigned b1) {
    asm("mma.sync.aligned.m16n8k8.row.col.f32.tf32.tf32.f32 "
        "{%0,%1,%2,%3}, {%4,%5,%6,%7}, {%8,%9}, {%0,%1,%2,%3};"
        : "+f"(c0), "+f"(c1), "+f"(c2), "+f"(c3)
        : "r"(a0), "r"(a1), "r"(a2), "r"(a3), "r"(b0), "r"(b1));
}

// swizzled V column: permute 8-float blocks by row&7
__device__ __forceinline__ int vswz(int row, int col) {
    return ((((col >> 3) ^ (row & 7)) << 3) | (col & 7));
}

__global__ __launch_bounds__(256, 2)
void attn_score(const float* __restrict__ Q, const float* __restrict__ K,
                const float* __restrict__ V, float* __restrict__ out_w)
{
    extern __shared__ float sm[];
    const int b  = blockIdx.y;
    const int x  = blockIdx.x;
    const int qt = x >> 5;
    const int kt = x & (NT - 1);
    const int q0 = qt * BQ, k0 = kt * BK;
    const int tid = threadIdx.x;

    if (kt > qt) {
        // strictly-upper tile: pure zero-fill of the weights region, then exit
        float* wg = out_w + ((size_t)(b * Ss + q0)) * Ss + k0;
        const float4 z = make_float4(0.f, 0.f, 0.f, 0.f);
        #pragma unroll
        for (int i = 0; i < 16; i++) {
            const int idx = tid + i * 256;
            const int row = idx >> 5;
            const int c4  = (idx & 31) << 2;
            *(float4*)(wg + (size_t)row * Ss + c4) = z;
        }
        return;
    }

    // ---- load Q, K, V; convert to tf32 bits while staging ----
    const float* Qg = Q + ((size_t)(b * Ss + q0)) * Dh;
    const float* Kg = K + ((size_t)(b * Ss + k0)) * Dh;
    const float* Vg = V + ((size_t)(b * Ss + k0)) * Dh;
    #pragma unroll
    for (int i = 0; i < 8; i++) {
        const int idx = tid + i * 256;
        const int row = idx >> 4;
        const int c4  = (idx & 15) << 2;

        float4 q4 = *(const float4*)(Qg + row * Dh + c4);
        q4.x = __uint_as_float(f2tf(q4.x)); q4.y = __uint_as_float(f2tf(q4.y));
        q4.z = __uint_as_float(f2tf(q4.z)); q4.w = __uint_as_float(f2tf(q4.w));
        *(float4*)(sm + OFF_Q + row * LDQ + c4) = q4;

        float4 k4 = *(const float4*)(Kg + row * Dh + c4);
        k4.x = __uint_as_float(f2tf(k4.x)); k4.y = __uint_as_float(f2tf(k4.y));
        k4.z = __uint_as_float(f2tf(k4.z)); k4.w = __uint_as_float(f2tf(k4.w));
        *(float4*)(sm + OFF_K + row * LDQ + c4) = k4;

        float4 v4 = *(const float4*)(Vg + row * Dh + c4);
        v4.x = __uint_as_float(f2tf(v4.x)); v4.y = __uint_as_float(f2tf(v4.y));
        v4.z = __uint_as_float(f2tf(v4.z)); v4.w = __uint_as_float(f2tf(v4.w));
        *(float4*)(sm + OFF_V + row * 64 + vswz(row, c4)) = v4;
    }
    __syncthreads();

    const int w = tid >> 5, lane = tid & 31;
    const int grp = lane >> 2, tig = lane & 3;

    // ---- QK^T: warp tile 64x32 (wm in {0,1}, wn in {0..3}), single tf32 pass ----
    const int wm = w & 1, wn = w >> 1;
    float acc[4][4][4];
    #pragma unroll
    for (int i = 0; i < 4; i++)
        #pragma unroll
        for (int j = 0; j < 4; j++)
            #pragma unroll
            for (int c = 0; c < 4; c++) acc[i][j][c] = 0.0f;

    #pragma unroll
    for (int kk = 0; kk < 8; kk++) {
        const int kb = kk * 8;
        unsigned ah[4][4];
        #pragma unroll
        for (int am = 0; am < 4; am++) {
            const int r = wm * 64 + am * 16 + grp;
            const float* p = sm + OFF_Q + r * LDQ + kb + tig;
            ah[am][0] = __float_as_uint(p[0]);
            ah[am][1] = __float_as_uint(p[8 * LDQ]);
            ah[am][2] = __float_as_uint(p[4]);
            ah[am][3] = __float_as_uint(p[8 * LDQ + 4]);
        }
        unsigned bh[4][2];
        #pragma unroll
        for (int an = 0; an < 4; an++) {
            const int c = wn * 32 + an * 8 + grp;
            const float* p = sm + OFF_K + c * LDQ + kb + tig;
            bh[an][0] = __float_as_uint(p[0]);
            bh[an][1] = __float_as_uint(p[4]);
        }
        #pragma unroll
        for (int am = 0; am < 4; am++)
            #pragma unroll
            for (int an = 0; an < 4; an++) {
                float* c = acc[am][an];
                mma8(c[0], c[1], c[2], c[3],
                     ah[am][0], ah[am][1], ah[am][2], ah[am][3],
                     bh[an][0], bh[an][1]);
            }
    }

    __syncthreads();   // all smem QK reads done; Ps may overwrite Q+K region

    // ---- mask + exp, stage tf32 P to smem, write fp32 weights, rowsums ----
    #pragma unroll
    for (int am = 0; am < 4; am++) {
        const int rl_loc = wm * 64 + am * 16 + grp;
        const int rowl = q0 + rl_loc;
        const int rowh = rowl + 8;
        float rlo = 0.0f, rhi = 0.0f;
        #pragma unroll
        for (int an = 0; an < 4; an++) {
            const int cl_loc = wn * 32 + an * 8 + 2 * tig;
            const int col = k0 + cl_loc;
            float* c = acc[am][an];
            float e0 = (col     <= rowl) ? __expf(c[0] * 0.125f) : 0.0f;
            float e1 = (col + 1 <= rowl) ? __expf(c[1] * 0.125f) : 0.0f;
            float e2 = (col     <= rowh) ? __expf(c[2] * 0.125f) : 0.0f;
            float e3 = (col + 1 <= rowh) ? __expf(c[3] * 0.125f) : 0.0f;
            rlo += e0 + e1; rhi += e2 + e3;

            *(float2*)(sm + OFF_PS + rl_loc * LDP + cl_loc) =
                make_float2(__uint_as_float(f2tf(e0)), __uint_as_float(f2tf(e1)));
            *(float2*)(sm + OFF_PS + (rl_loc + 8) * LDP + cl_loc) =
                make_float2(__uint_as_float(f2tf(e2)), __uint_as_float(f2tf(e3)));

            float* wg = out_w + ((size_t)(b * Ss + rowl)) * Ss + col;
            *(float2*)wg                    = make_float2(e0, e1);
            *(float2*)(wg + (size_t)8 * Ss) = make_float2(e2, e3);
        }
        rlo += __shfl_xor_sync(0xffffffffu, rlo, 1);
        rlo += __shfl_xor_sync(0xffffffffu, rlo, 2);
        rhi += __shfl_xor_sync(0xffffffffu, rhi, 1);
        rhi += __shfl_xor_sync(0xffffffffu, rhi, 2);
        if (tig == 0) {
            atomicAdd(&g_rsum[b * Ss + rowl], rlo);
            atomicAdd(&g_rsum[b * Ss + rowh], rhi);
        }
    }
    __syncthreads();   // Ps fully staged

    // ---- PV partial: warp tile 32x32 (wm2 in {0..3}, wn2 in {0,1}) ----
    const int wm2 = w >> 1, wn2 = w & 1;
    float vacc[2][4][4];
    #pragma unroll
    for (int i = 0; i < 2; i++)
        #pragma unroll
        for (int j = 0; j < 4; j++)
            #pragma unroll
            for (int c = 0; c < 4; c++) vacc[i][j][c] = 0.0f;

    #pragma unroll
    for (int ks = 0; ks < 16; ks++) {
        const int kb = ks * 8;
        unsigned pa[2][4];
        #pragma unroll
        for (int am = 0; am < 2; am++) {
            const int r = wm2 * 32 + am * 16 + grp;
            const float* p = sm + OFF_PS + r * LDP + kb + tig;
            pa[am][0] = __float_as_uint(p[0]);
            pa[am][1] = __float_as_uint(p[8 * LDP]);
            pa[am][2] = __float_as_uint(p[4]);
            pa[am][3] = __float_as_uint(p[8 * LDP + 4]);
        }
        unsigned vb[4][2];
        #pragma unroll
        for (int an = 0; an < 4; an++) {
            const int c = wn2 * 32 + an * 8 + grp;
            const int r0v = kb + tig, r1v = kb + tig + 4;
            vb[an][0] = __float_as_uint(sm[OFF_V + r0v * 64 + vswz(r0v, c)]);
            vb[an][1] = __float_as_uint(sm[OFF_V + r1v * 64 + vswz(r1v, c)]);
        }
        #pragma unroll
        for (int am = 0; am < 2; am++)
            #pragma unroll
            for (int an = 0; an < 4; an++) {
                float* c = vacc[am][an];
                mma8(c[0], c[1], c[2], c[3],
                     pa[am][0], pa[am][1], pa[am][2], pa[am][3],
                     vb[an][0], vb[an][1]);
            }
    }

    #pragma unroll
    for (int am = 0; am < 2; am++) {
        const int gl = b * Ss + q0 + wm2 * 32 + am * 16 + grp;
        const int gh = gl + 8;
        #pragma unroll
        for (int an = 0; an < 4; an++) {
            const int col = wn2 * 32 + an * 8 + 2 * tig;
            float* c = vacc[am][an];
            atomicAdd(&g_vec[(size_t)gl * Dh + col],     c[0]);
            atomicAdd(&g_vec[(size_t)gl * Dh + col + 1], c[1]);
            atomicAdd(&g_vec[(size_t)gh * Dh + col],     c[2]);
            atomicAdd(&g_vec[(size_t)gh * Dh + col + 1], c[3]);
        }
    }
}

// vec = g_vec / rowsum ; also publish g_inv
__global__ __launch_bounds__(256)
void finalize(float* __restrict__ out_vec)
{
    const int idx = blockIdx.x * 256 + threadIdx.x;
    const int row = idx >> 4;
    const int c4  = (idx & 15) << 2;
    const float inv = 1.0f / g_rsum[row];
    if ((idx & 15) == 0) g_inv[row] = inv;
    float4 v = *(const float4*)(g_vec + (size_t)row * Dh + c4);
    v.x *= inv; v.y *= inv; v.z *= inv; v.w *= inv;
    *(float4*)(out_vec + (size_t)row * Dh + c4) = v;
}

// Scale causal tiles by 1/rowsum (tile-parallel; only kt<=qt tiles exist here).
__global__ __launch_bounds__(256)
void norm_w(float* __restrict__ w)
{
    const int b = blockIdx.y;
    const int x = blockIdx.x;

    int qt = (int)((sqrtf(8.0f * (float)x + 1.0f) - 1.0f) * 0.5f);
    while ((qt + 1) * (qt + 2) / 2 <= x) qt++;
    while (qt * (qt + 1) / 2 > x) qt--;
    const int kt = x - qt * (qt + 1) / 2;

    const int tid = threadIdx.x;
    float* wg = w + ((size_t)(b * Ss + qt * BQ)) * Ss + kt * BK;
    const float* invp = g_inv + b * Ss + qt * BQ;

    #pragma unroll
    for (int i = 0; i < 16; i++) {
        const int idx = tid + i * 256;
        const int row = idx >> 5;
        const int c4  = (idx & 31) << 2;
        const float inv = invp[row];
        float4 v = *(const float4*)(wg + (size_t)row * Ss + c4);
        v.x *= inv; v.y *= inv; v.z *= inv; v.w *= inv;
        *(float4*)(wg + (size_t)row * Ss + c4) = v;
    }
}

extern "C" void kernel_launch(void* const* d_in, const int* in_sizes, int n_in,
                              void* d_out, int out_size)
{
    const float* Q = (const float*)d_in[0];
    const float* K = (const float*)d_in[1];
    const float* V = (const float*)d_in[2];

    float* out_vec = (float*)d_out;
    float* out_w   = out_vec + (size_t)Bb * Ss * Dh;

    void* p_rsum = nullptr;
    void* p_vec  = nullptr;
    cudaGetSymbolAddress(&p_rsum, g_rsum);
    cudaGetSymbolAddress(&p_vec,  g_vec);
    cudaMemsetAsync(p_rsum, 0, sizeof(float) * Bb * Ss);
    cudaMemsetAsync(p_vec,  0, sizeof(float) * Bb * Ss * Dh);

    cudaFuncSetAttribute(attn_score, cudaFuncAttributeMaxDynamicSharedMemorySize,
                         SMEM_BYTES);

    dim3 gridA(NT * NT, Bb);                       // all (qt,kt); upper tiles zero-fill
    attn_score<<<gridA, 256, SMEM_BYTES>>>(Q, K, V, out_w);

    finalize<<<(Bb * Ss * Dh / 4) / 256, 256>>>(out_vec);

    const int ncausal = NT * (NT + 1) / 2;         // 528
    dim3 gridN(ncausal, Bb);
    norm_w<<<gridN, 256>>>(out_w);
}

// round 6
// speedup vs baseline: 3.7793x; 1.1219x over previous
#include <cuda_runtime.h>
#include <cuda_fp16.h>
#include <cstdint>
#include <math.h>

// Causal attention, B=4, S=4096, D=64, fp32 in/out.
// out = [ attn_vec (B*S*64) | attn_weights (B*S*S) ]
// Datapath: Q/K/V/P in smem as fp16 (same 11-bit mantissa as tf32);
// QK^T and PV via mma.m16n8k16.f16 with fp32 accumulate.
// Weights written as fp32 exp values (unnormalized), rescaled by norm_w.

constexpr int Bb = 4;
constexpr int Ss = 4096;
constexpr int Dh = 64;
constexpr int BQ = 128;
constexpr int BK = 128;
constexpr int NT = Ss / BQ;          // 32

// u32-word offsets in dynamic smem (all arrays fp16, accessed as u32 words)
constexpr int OFFW_Q = 0;            // Qh [128][64] halves, pitch 32 words
constexpr int OFFW_K = 4096;         // Kh [128][64] halves, pitch 32 words
constexpr int OFFW_P = 0;            // Ph [128][128] halves, pitch 64 words (overlays Q+K)
constexpr int OFFW_V = 8192;         // Vt [64][128] halves (d-major), pitch 64 words
constexpr int SMEM_WORDS = 12288;
constexpr int SMEM_BYTES = SMEM_WORDS * 4;   // 49152

__device__ float g_rsum[Bb * Ss];
__device__ float g_inv [Bb * Ss];
__device__ float g_vec [Bb * Ss * Dh];

__device__ __forceinline__ unsigned packh2(float lo, float hi) {
    __half2 h = __floats2half2_rn(lo, hi);
    return *(unsigned*)&h;
}

__device__ __forceinline__ void mma16(float& c0, float& c1, float& c2, float& c3,
                                      unsigned a0, unsigned a1, unsigned a2, unsigned a3,
                                      unsigned b0, unsigned b1) {
    asm("mma.sync.aligned.m16n8k16.row.col.f32.f16.f16.f32 "
        "{%0,%1,%2,%3}, {%4,%5,%6,%7}, {%8,%9}, {%0,%1,%2,%3};"
        : "+f"(c0), "+f"(c1), "+f"(c2), "+f"(c3)
        : "r"(a0), "r"(a1), "r"(a2), "r"(a3), "r"(b0), "r"(b1));
}

__global__ __launch_bounds__(256, 2)
void attn_score(const float* __restrict__ Q, const float* __restrict__ K,
                const float* __restrict__ V, float* __restrict__ out_w)
{
    extern __shared__ __align__(16) unsigned smu[];
    __half* smh = (__half*)smu;

    const int b  = blockIdx.y;
    const int x  = blockIdx.x;
    const int qt = x >> 5;
    const int kt = x & (NT - 1);
    const int q0 = qt * BQ, k0 = kt * BK;
    const int tid = threadIdx.x;

    if (kt > qt) {
        // strictly-upper tile: pure zero-fill of the weights region, then exit
        float* wg = out_w + ((size_t)(b * Ss + q0)) * Ss + k0;
        const float4 z = make_float4(0.f, 0.f, 0.f, 0.f);
        #pragma unroll
        for (int i = 0; i < 16; i++) {
            const int idx = tid + i * 256;
            const int row = idx >> 5;
            const int c4  = (idx & 31) << 2;
            *(float4*)(wg + (size_t)row * Ss + c4) = z;
        }
        return;
    }

    // ---- stage Q, K (fp16, swizzled, pitch 32 words) ----
    const float* Qg = Q + ((size_t)(b * Ss + q0)) * Dh;
    const float* Kg = K + ((size_t)(b * Ss + k0)) * Dh;
    const float* Vg = V + ((size_t)(b * Ss + k0)) * Dh;
    #pragma unroll
    for (int i = 0; i < 8; i++) {
        const int idx = tid + i * 256;
        const int row = idx >> 4;
        const int c4  = (idx & 15) << 2;
        const int w0  = c4 >> 1;                      // even
        const int sw  = (row & 7) << 2;
        const int bw  = row * 32 + (w0 ^ sw);         // swizzle preserves +1 adjacency

        float4 q4 = *(const float4*)(Qg + row * Dh + c4);
        *(uint2*)(smu + OFFW_Q + bw) = make_uint2(packh2(q4.x, q4.y), packh2(q4.z, q4.w));

        float4 k4 = *(const float4*)(Kg + row * Dh + c4);
        *(uint2*)(smu + OFFW_K + bw) = make_uint2(packh2(k4.x, k4.y), packh2(k4.z, k4.w));
    }
    // ---- stage V transposed: Vt[d][k] halves, pitch 64 words, swizzled ----
    #pragma unroll
    for (int i = 0; i < 8; i++) {
        const int idx = tid + i * 256;
        const int k   = idx & 127;
        const int d4  = (idx >> 7) << 2;
        float4 v4 = *(const float4*)(Vg + k * Dh + d4);
        float vv[4] = {v4.x, v4.y, v4.z, v4.w};
        #pragma unroll
        for (int j = 0; j < 4; j++) {
            const int d = d4 + j;
            const int w = (k >> 1) ^ ((d & 7) << 2);
            smh[((OFFW_V + d * 64 + w) << 1) + (k & 1)] = __float2half_rn(vv[j]);
        }
    }
    __syncthreads();

    const int w = tid >> 5, lane = tid & 31;
    const int grp = lane >> 2, tig = lane & 3;
    const int sw  = grp << 2;

    // ---- QK^T: warp tile 64x32 (wm in {0,1}, wn in {0..3}) ----
    const int wm = w & 1, wn = w >> 1;
    float acc[4][4][4];
    #pragma unroll
    for (int i = 0; i < 4; i++)
        #pragma unroll
        for (int j = 0; j < 4; j++)
            #pragma unroll
            for (int c = 0; c < 4; c++) acc[i][j][c] = 0.0f;

    #pragma unroll
    for (int kk = 0; kk < 4; kk++) {
        const int w0 = kk * 8 + tig;
        unsigned ah[4][4];
        #pragma unroll
        for (int am = 0; am < 4; am++) {
            const int r = wm * 64 + am * 16 + grp;
            ah[am][0] = smu[OFFW_Q + r * 32 + (w0 ^ sw)];
            ah[am][1] = smu[OFFW_Q + (r + 8) * 32 + (w0 ^ sw)];
            ah[am][2] = smu[OFFW_Q + r * 32 + ((w0 + 4) ^ sw)];
            ah[am][3] = smu[OFFW_Q + (r + 8) * 32 + ((w0 + 4) ^ sw)];
        }
        unsigned bh[4][2];
        #pragma unroll
        for (int an = 0; an < 4; an++) {
            const int n = wn * 32 + an * 8 + grp;
            bh[an][0] = smu[OFFW_K + n * 32 + (w0 ^ sw)];
            bh[an][1] = smu[OFFW_K + n * 32 + ((w0 + 4) ^ sw)];
        }
        #pragma unroll
        for (int am = 0; am < 4; am++)
            #pragma unroll
            for (int an = 0; an < 4; an++) {
                float* c = acc[am][an];
                mma16(c[0], c[1], c[2], c[3],
                      ah[am][0], ah[am][1], ah[am][2], ah[am][3],
                      bh[an][0], bh[an][1]);
            }
    }

    __syncthreads();   // QK reads of Qh/Kh done; Ph may overwrite

    // ---- mask + exp; stage fp16 P; write fp32 weights; rowsums ----
    #pragma unroll
    for (int am = 0; am < 4; am++) {
        const int rl_loc = wm * 64 + am * 16 + grp;
        const int rowl = q0 + rl_loc;
        const int rowh = rowl + 8;
        float rlo = 0.0f, rhi = 0.0f;
        #pragma unroll
        for (int an = 0; an < 4; an++) {
            const int cl_loc = wn * 32 + an * 8 + 2 * tig;
            const int col = k0 + cl_loc;
            float* c = acc[am][an];
            float e0 = (col     <= rowl) ? __expf(c[0] * 0.125f) : 0.0f;
            float e1 = (col + 1 <= rowl) ? __expf(c[1] * 0.125f) : 0.0f;
            float e2 = (col     <= rowh) ? __expf(c[2] * 0.125f) : 0.0f;
            float e3 = (col + 1 <= rowh) ? __expf(c[3] * 0.125f) : 0.0f;
            rlo += e0 + e1; rhi += e2 + e3;

            const int wcol = (cl_loc >> 1) ^ sw;
            smu[OFFW_P + rl_loc * 64 + wcol]       = packh2(e0, e1);
            smu[OFFW_P + (rl_loc + 8) * 64 + wcol] = packh2(e2, e3);

            float* wg = out_w + ((size_t)(b * Ss + rowl)) * Ss + col;
            *(float2*)wg                    = make_float2(e0, e1);
            *(float2*)(wg + (size_t)8 * Ss) = make_float2(e2, e3);
        }
        rlo += __shfl_xor_sync(0xffffffffu, rlo, 1);
        rlo += __shfl_xor_sync(0xffffffffu, rlo, 2);
        rhi += __shfl_xor_sync(0xffffffffu, rhi, 1);
        rhi += __shfl_xor_sync(0xffffffffu, rhi, 2);
        if (tig == 0) {
            atomicAdd(&g_rsum[b * Ss + rowl], rlo);
            atomicAdd(&g_rsum[b * Ss + rowh], rhi);
        }
    }
    __syncthreads();   // Ph fully staged

    // ---- PV partial: warp tile 32x32 (wm2 in {0..3}, wn2 in {0,1}) ----
    const int wm2 = w >> 1, wn2 = w & 1;
    float vacc[2][4][4];
    #pragma unroll
    for (int i = 0; i < 2; i++)
        #pragma unroll
        for (int j = 0; j < 4; j++)
            #pragma unroll
            for (int c = 0; c < 4; c++) vacc[i][j][c] = 0.0f;

    #pragma unroll
    for (int ks = 0; ks < 8; ks++) {
        const int w0 = ks * 8 + tig;
        unsigned pa[2][4];
        #pragma unroll
        for (int am = 0; am < 2; am++) {
            const int r = wm2 * 32 + am * 16 + grp;
            pa[am][0] = smu[OFFW_P + r * 64 + (w0 ^ sw)];
            pa[am][1] = smu[OFFW_P + (r + 8) * 64 + (w0 ^ sw)];
            pa[am][2] = smu[OFFW_P + r * 64 + ((w0 + 4) ^ sw)];
            pa[am][3] = smu[OFFW_P + (r + 8) * 64 + ((w0 + 4) ^ sw)];
        }
        unsigned vb[4][2];
        #pragma unroll
        for (int an = 0; an < 4; an++) {
            const int d = wn2 * 32 + an * 8 + grp;
            vb[an][0] = smu[OFFW_V + d * 64 + (w0 ^ sw)];
            vb[an][1] = smu[OFFW_V + d * 64 + ((w0 + 4) ^ sw)];
        }
        #pragma unroll
        for (int am = 0; am < 2; am++)
            #pragma unroll
            for (int an = 0; an < 4; an++) {
                float* c = vacc[am][an];
                mma16(c[0], c[1], c[2], c[3],
                      pa[am][0], pa[am][1], pa[am][2], pa[am][3],
                      vb[an][0], vb[an][1]);
            }
    }

    #pragma unroll
    for (int am = 0; am < 2; am++) {
        const int gl = b * Ss + q0 + wm2 * 32 + am * 16 + grp;
        const int gh = gl + 8;
        #pragma unroll
        for (int an = 0; an < 4; an++) {
            const int col = wn2 * 32 + an * 8 + 2 * tig;
            float* c = vacc[am][an];
            atomicAdd(&g_vec[(size_t)gl * Dh + col],     c[0]);
            atomicAdd(&g_vec[(size_t)gl * Dh + col + 1], c[1]);
            atomicAdd(&g_vec[(size_t)gh * Dh + col],     c[2]);
            atomicAdd(&g_vec[(size_t)gh * Dh + col + 1], c[3]);
        }
    }
}

// vec = g_vec / rowsum ; also publish g_inv
__global__ __launch_bounds__(256)
void finalize(float* __restrict__ out_vec)
{
    const int idx = blockIdx.x * 256 + threadIdx.x;
    const int row = idx >> 4;
    const int c4  = (idx & 15) << 2;
    const float inv = 1.0f / g_rsum[row];
    if ((idx & 15) == 0) g_inv[row] = inv;
    float4 v = *(const float4*)(g_vec + (size_t)row * Dh + c4);
    v.x *= inv; v.y *= inv; v.z *= inv; v.w *= inv;
    *(float4*)(out_vec + (size_t)row * Dh + c4) = v;
}

// Scale causal tiles by 1/rowsum (tile-parallel; only kt<=qt tiles exist here).
__global__ __launch_bounds__(256)
void norm_w(float* __restrict__ w)
{
    const int b = blockIdx.y;
    const int x = blockIdx.x;

    int qt = (int)((sqrtf(8.0f * (float)x + 1.0f) - 1.0f) * 0.5f);
    while ((qt + 1) * (qt + 2) / 2 <= x) qt++;
    while (qt * (qt + 1) / 2 > x) qt--;
    const int kt = x - qt * (qt + 1) / 2;

    const int tid = threadIdx.x;
    float* wg = w + ((size_t)(b * Ss + qt * BQ)) * Ss + kt * BK;
    const float* invp = g_inv + b * Ss + qt * BQ;

    #pragma unroll
    for (int i = 0; i < 16; i++) {
        const int idx = tid + i * 256;
        const int row = idx >> 5;
        const int c4  = (idx & 31) << 2;
        const float inv = invp[row];
        float4 v = *(const float4*)(wg + (size_t)row * Ss + c4);
        v.x *= inv; v.y *= inv; v.z *= inv; v.w *= inv;
        *(float4*)(wg + (size_t)row * Ss + c4) = v;
    }
}

extern "C" void kernel_launch(void* const* d_in, const int* in_sizes, int n_in,
                              void* d_out, int out_size)
{
    const float* Q = (const float*)d_in[0];
    const float* K = (const float*)d_in[1];
    const float* V = (const float*)d_in[2];

    float* out_vec = (float*)d_out;
    float* out_w   = out_vec + (size_t)Bb * Ss * Dh;

    void* p_rsum = nullptr;
    void* p_vec  = nullptr;
    cudaGetSymbolAddress(&p_rsum, g_rsum);
    cudaGetSymbolAddress(&p_vec,  g_vec);
    cudaMemsetAsync(p_rsum, 0, sizeof(float) * Bb * Ss);
    cudaMemsetAsync(p_vec,  0, sizeof(float) * Bb * Ss * Dh);

    cudaFuncSetAttribute(attn_score, cudaFuncAttributeMaxDynamicSharedMemorySize,
                         SMEM_BYTES);

    dim3 gridA(NT * NT, Bb);                       // all (qt,kt); upper tiles zero-fill
    attn_score<<<gridA, 256, SMEM_BYTES>>>(Q, K, V, out_w);

    finalize<<<(Bb * Ss * Dh / 4) / 256, 256>>>(out_vec);

    const int ncausal = NT * (NT + 1) / 2;         // 528
    dim3 gridN(ncausal, Bb);
    norm_w<<<gridN, 256>>>(out_w);
}